// round 14
// baseline (speedup 1.0000x reference)
#include <cuda_runtime.h>
#include <cuda_bf16.h>
#include <math.h>

// Problem dims
#define Nn    128
#define Tt    32
#define TCAP  33
#define Dd    400
#define Ww    512
#define Hh    1024
#define Vv    10000
#define Gg    4096   // 4*H

// ---------------- device scratch (static, allocation-guard compliant) ----------------
__device__ __align__(16) float g_A[Nn * 16 * Hh];              // A_flat [n][l][h], 8 MB
__device__ __align__(16) float g_h[Nn * Hh];                   // current hidden
__device__ __align__(16) float g_c[Nn * Hh];                   // current cell
__device__ __align__(16) float g_attnP[Nn * Gg];               // (attn @ Wattn), 2 MB
__device__ __align__(16) float g_xw[(size_t)Tt * Nn * Gg];     // x_t @ Wx, rows t*128+n, 64 MB
__device__ __align__(16) float g_P[(size_t)Nn * 16 * Gg];      // A_flat @ Wattn, rows n*16+l, 32 MB
__device__ __align__(16) float g_zs[2 * Nn * Gg];              // split-K partials of h@Wh, 4 MB
__device__ __align__(16) float g_hn[(size_t)Tt * Nn * Hh];     // hidden states, rows t*128+n, 16 MB
__device__ __align__(16) float g_scores[(size_t)Tt * Nn * Vv]; // 4096 x 10000 logits, 164 MB
__device__ __align__(16) float g_nll[Tt * Nn];

// ---------------- helpers ----------------
__device__ __forceinline__ unsigned tf32cvt(float f) {
    unsigned u;
    asm("cvt.rna.tf32.f32 %0, %1;" : "=r"(u) : "f"(f));
    return u;
}
__device__ __forceinline__ void mma_tf32(float* c, const unsigned* a, const unsigned* b) {
    asm("mma.sync.aligned.m16n8k8.row.col.f32.tf32.tf32.f32 "
        "{%0,%1,%2,%3}, {%4,%5,%6,%7}, {%8,%9}, {%0,%1,%2,%3};"
        : "+f"(c[0]), "+f"(c[1]), "+f"(c[2]), "+f"(c[3])
        : "r"(a[0]), "r"(a[1]), "r"(a[2]), "r"(a[3]), "r"(b[0]), "r"(b[1]));
}
__device__ __forceinline__ uint4 tf32x4(float4 v) {
    uint4 q;
    q.x = tf32cvt(v.x); q.y = tf32cvt(v.y); q.z = tf32cvt(v.z); q.w = tf32cvt(v.w);
    return q;
}

// ---------------- 1) feature projection: A[n][l][h] = sum_d F[n][d][l]*Wp[d][h] + bp[h] ----------------
__global__ void proj_kernel(const float* __restrict__ features,
                            const float* __restrict__ W_proj,
                            const float* __restrict__ b_proj) {
    __shared__ float Fs[Dd * 16];
    int n  = blockIdx.y;
    int h0 = blockIdx.x * 128;
    int t  = threadIdx.x;

    const float* F = features + (size_t)n * Dd * 16;
    for (int i = t; i < Dd * 16; i += 256) Fs[i] = F[i];
    __syncthreads();

    int h  = h0 + (t & 127);
    int lb = (t >> 7) * 8;
    float acc[8];
    #pragma unroll
    for (int i = 0; i < 8; i++) acc[i] = 0.f;

    for (int d = 0; d < Dd; d++) {
        float w = W_proj[(size_t)d * Hh + h];
        #pragma unroll
        for (int i = 0; i < 8; i++) acc[i] += Fs[d * 16 + lb + i] * w;
    }
    float bp = b_proj[h];
    #pragma unroll
    for (int i = 0; i < 8; i++)
        g_A[(size_t)n * 16 * Hh + (lb + i) * Hh + h] = acc[i] + bp;
}

// ---------------- 2) h0 = mean over l; init h and c ----------------
__global__ void h0_kernel() {
    int idx = blockIdx.x * blockDim.x + threadIdx.x;
    if (idx >= Nn * Hh) return;
    int n = idx >> 10;
    float s = 0.f;
    #pragma unroll
    for (int l = 0; l < 16; l++) s += g_A[(size_t)n * 16 * Hh + l * Hh + (idx & (Hh - 1))];
    s *= (1.0f / 16.0f);
    g_h[idx] = s;
    g_c[idx] = s;
}

// ---------------- TF32 tensor-core GEMM body: C[M x NTILE] = A[M x K] * B[K x NTILE] ----------------
// Block tile 128 x NT (NT = 64 or 128), BK=32, 256 threads. Double-buffered smem:
// per K-tile: gmem-prefetch(next) -> compute(cur) -> store(next buf) -> ONE syncthreads.
// NT=64 : warps 4M x 2N, warp tile 32x32 (mt=2)  -- used for MODE 3 (step GEMM)
// NT=128: warps 2M x 4N, warp tile 64x32 (mt=4)  -- batch GEMMs
// MODE 0: xw   A = embedding gather (K=512),  B=Wx,      C=g_xw
// MODE 1: P    A = g_A   (2048 rows, K=1024), B=Wattn,   C=g_P
// MODE 2: voc  A = g_hn  (4096 rows, K=1024), B=W_vocab, C=g_scores (+bias, col guard)
// MODE 3: hWh  A = g_h   (128 rows),  split-K=2 over K=1024 via 'by', C=g_zs
template<int MODE, int NT>
__device__ __forceinline__ void gemm_body(
    int bx, int by,
    const float* __restrict__ Bmat,
    const int*   __restrict__ captions,
    const float* __restrict__ W_embed,
    const float* __restrict__ bias,
    unsigned (*As)[128][36], unsigned (*Bs)[32][NT + 8])
{
    constexpr int KLEN  = (MODE == 0 || MODE == 3) ? 512 : 1024;
    constexpr int NITER = KLEN / 32;
    constexpr int LDB   = (MODE == 2) ? Vv : Gg;
    constexpr int LDC   = (MODE == 2) ? Vv : Gg;
    constexpr int MT    = (NT == 64) ? 2 : 4;       // m16 fragments per warp
    constexpr int NB4   = (NT == 64) ? 2 : 4;       // float4 chunks per thread in B fill

    const int tid  = threadIdx.x;
    const int lane = tid & 31;
    const int warp = tid >> 5;
    const int wm   = (NT == 64) ? (warp >> 1) * 32 : (warp >> 2) * 64;
    const int wn   = (NT == 64) ? (warp & 1) * 32  : (warp & 3) * 32;
    const int gid  = lane >> 2;            // 0..7
    const int tig  = lane & 3;             // 0..3
    const int n0   = bx * NT;

    int m0, kbase;
    float* C;
    if (MODE == 3) {
        m0 = 0; kbase = by * 512;
        C = g_zs + (size_t)by * (Nn * Gg);
    } else {
        m0 = by * 128; kbase = 0;
        C = (MODE == 0) ? g_xw : ((MODE == 1) ? g_P : g_scores);
    }

    // ---- A fill: thread owns row lm, 16 consecutive k at offset lkk ----
    const int lm  = tid >> 1;              // 0..127
    const int lkk = (tid & 1) * 16;        // 0 or 16
    const float* aptr;
    {
        int gr = m0 + lm;
        const float* rowp;
        if (MODE == 0) {
            int tok = captions[(gr & 127) * TCAP + (gr >> 7)];
            rowp = W_embed + (size_t)tok * Ww;
        } else if (MODE == 1) {
            rowp = g_A + (size_t)gr * Hh;
        } else if (MODE == 2) {
            rowp = g_hn + (size_t)gr * Hh;
        } else {
            rowp = g_h + (size_t)gr * Hh;
        }
        aptr = rowp + kbase + lkk;
    }

    // ---- B fill: thread owns k-row bk, NB4*4 consecutive cols at bj ----
    const int bk = tid >> 3;               // 0..31
    const int bj = (tid & 7) * (NB4 * 4);
    const float* bptr = Bmat + (size_t)(kbase + bk) * LDB + n0 + bj;
    const bool bok = (MODE != 2) || (n0 + bj + NB4 * 4 - 1 < Vv);

    // ---- prologue: load tile 0, store to buffer 0, sync ----
    float4 av0, av1, av2, av3;
    float4 bu[NB4];
    av0 = *(const float4*)(aptr);     av1 = *(const float4*)(aptr + 4);
    av2 = *(const float4*)(aptr + 8); av3 = *(const float4*)(aptr + 12);
    aptr += 32;
    if (bok) {
        #pragma unroll
        for (int q = 0; q < NB4; q++) bu[q] = *(const float4*)(bptr + 4 * q);
    } else {
        #pragma unroll
        for (int q = 0; q < NB4; q++) bu[q] = make_float4(0.f, 0.f, 0.f, 0.f);
    }
    bptr += (size_t)32 * LDB;

    *(uint4*)&As[0][lm][lkk + 0]  = tf32x4(av0);
    *(uint4*)&As[0][lm][lkk + 4]  = tf32x4(av1);
    *(uint4*)&As[0][lm][lkk + 8]  = tf32x4(av2);
    *(uint4*)&As[0][lm][lkk + 12] = tf32x4(av3);
    #pragma unroll
    for (int q = 0; q < NB4; q++)
        *(uint4*)&Bs[0][bk][bj + 4 * q] = tf32x4(bu[q]);
    __syncthreads();

    float acc[MT][4][4];
    #pragma unroll
    for (int mt = 0; mt < MT; mt++)
        #pragma unroll
        for (int nt = 0; nt < 4; nt++)
            #pragma unroll
            for (int q = 0; q < 4; q++) acc[mt][nt][q] = 0.f;

    for (int it = 0; it < NITER; it++) {
        const int cur  = it & 1;
        const bool more = (it + 1 < NITER);

        // ---- gmem prefetch of next tile (latency hidden under compute) ----
        if (more) {
            av0 = *(const float4*)(aptr);     av1 = *(const float4*)(aptr + 4);
            av2 = *(const float4*)(aptr + 8); av3 = *(const float4*)(aptr + 12);
            aptr += 32;
            if (bok) {
                #pragma unroll
                for (int q = 0; q < NB4; q++) bu[q] = *(const float4*)(bptr + 4 * q);
            }
            bptr += (size_t)32 * LDB;
        }

        // ---- compute: 4 k8 steps from buffer cur ----
        #pragma unroll
        for (int k8 = 0; k8 < 4; k8++) {
            const int kk = k8 * 8;
            unsigned bfr[4][2];
            #pragma unroll
            for (int nt = 0; nt < 4; nt++) {
                int ccol = wn + nt * 8 + gid;
                bfr[nt][0] = Bs[cur][kk + tig][ccol];
                bfr[nt][1] = Bs[cur][kk + tig + 4][ccol];
            }
            #pragma unroll
            for (int half = 0; half < MT / 2; half++) {
                unsigned afr[2][4];
                #pragma unroll
                for (int m2 = 0; m2 < 2; m2++) {
                    int r = wm + (half * 2 + m2) * 16 + gid;
                    afr[m2][0] = As[cur][r][kk + tig];
                    afr[m2][1] = As[cur][r + 8][kk + tig];
                    afr[m2][2] = As[cur][r][kk + tig + 4];
                    afr[m2][3] = As[cur][r + 8][kk + tig + 4];
                }
                #pragma unroll
                for (int m2 = 0; m2 < 2; m2++)
                    #pragma unroll
                    for (int nt = 0; nt < 4; nt++)
                        mma_tf32(acc[half * 2 + m2][nt], afr[m2], bfr[nt]);
            }
        }

        // ---- store next tile to the other buffer; single barrier ----
        if (more) {
            const int nxt = cur ^ 1;
            *(uint4*)&As[nxt][lm][lkk + 0]  = tf32x4(av0);
            *(uint4*)&As[nxt][lm][lkk + 4]  = tf32x4(av1);
            *(uint4*)&As[nxt][lm][lkk + 8]  = tf32x4(av2);
            *(uint4*)&As[nxt][lm][lkk + 12] = tf32x4(av3);
            #pragma unroll
            for (int q = 0; q < NB4; q++)
                *(uint4*)&Bs[nxt][bk][bj + 4 * q] = tf32x4(bu[q]);
            __syncthreads();
        }
    }

    // ---- epilogue: c-frag layout -> gmem (float2 stores; col even, Vv even) ----
    #pragma unroll
    for (int mt = 0; mt < MT; mt++) {
        #pragma unroll
        for (int nt = 0; nt < 4; nt++) {
            int col = n0 + wn + nt * 8 + 2 * tig;
            if (MODE != 2 || col < Vv) {
                float b0 = 0.f, b1 = 0.f;
                if (MODE == 2) { b0 = bias[col]; b1 = bias[col + 1]; }
                int r0 = m0 + wm + mt * 16 + gid;
                float2 lo = make_float2(acc[mt][nt][0] + b0, acc[mt][nt][1] + b1);
                float2 hi = make_float2(acc[mt][nt][2] + b0, acc[mt][nt][3] + b1);
                *(float2*)&C[(size_t)r0 * LDC + col]       = lo;
                *(float2*)&C[(size_t)(r0 + 8) * LDC + col] = hi;
            }
        }
    }
}

template<int MODE, int NT>
__global__ void __launch_bounds__(256, 2) gemm_tf32(
    const float* __restrict__ Bmat,
    const int*   __restrict__ captions,
    const float* __restrict__ W_embed,
    const float* __restrict__ bias)
{
    __shared__ unsigned As[2][128][36];
    __shared__ unsigned Bs[2][32][NT + 8];
    gemm_body<MODE, NT>(blockIdx.x, blockIdx.y, Bmat, captions, W_embed, bias, As, Bs);
}

// ---------------- attention body: w = softmax(h.A/sqrt(H)); attnP = sum_l w_l P[n,l,:] ----------------
__device__ __forceinline__ void attn_body(int n, float* ph, float* scbuf) {
    float* sc  = scbuf;
    float* wsm = scbuf + 16;
    int t = threadIdx.x;

    #pragma unroll
    for (int i = 0; i < 4; i++) ph[t + 256 * i] = g_h[(size_t)n * Hh + t + 256 * i];
    __syncthreads();

    int warp = t >> 5, lane = t & 31;
    #pragma unroll
    for (int li = 0; li < 2; li++) {
        int l = warp + 8 * li;
        const float* Arow = g_A + (size_t)n * 16 * Hh + (size_t)l * Hh;
        float s = 0.f;
        for (int h = lane; h < Hh; h += 32) s += ph[h] * Arow[h];
        #pragma unroll
        for (int o = 16; o > 0; o >>= 1) s += __shfl_xor_sync(0xffffffff, s, o);
        if (lane == 0) sc[l] = s;
    }
    __syncthreads();

    if (t < 32) {
        float v = (t < 16) ? sc[t] * 0.03125f : -1e30f;   // 1/sqrt(1024)
        float m = v;
        #pragma unroll
        for (int o = 16; o > 0; o >>= 1) m = fmaxf(m, __shfl_xor_sync(0xffffffff, m, o));
        float e = (t < 16) ? expf(v - m) : 0.f;
        float se = e;
        #pragma unroll
        for (int o = 16; o > 0; o >>= 1) se += __shfl_xor_sync(0xffffffff, se, o);
        if (t < 16) wsm[t] = e / se;
    }
    __syncthreads();

    const float* Pn = g_P + (size_t)n * 16 * Gg;
    float w0 = wsm[0], w1 = wsm[1], w2 = wsm[2], w3 = wsm[3];
    float w4 = wsm[4], w5 = wsm[5], w6 = wsm[6], w7 = wsm[7];
    float w8 = wsm[8], w9 = wsm[9], wa = wsm[10], wb = wsm[11];
    float wc = wsm[12], wd = wsm[13], we = wsm[14], wf = wsm[15];
    for (int c = t; c < Gg; c += 256) {
        float a = w0 * Pn[c]           + w1 * Pn[c + Gg]       + w2 * Pn[c + 2 * Gg]  + w3 * Pn[c + 3 * Gg]
                + w4 * Pn[c + 4 * Gg]  + w5 * Pn[c + 5 * Gg]   + w6 * Pn[c + 6 * Gg]  + w7 * Pn[c + 7 * Gg]
                + w8 * Pn[c + 8 * Gg]  + w9 * Pn[c + 9 * Gg]   + wa * Pn[c + 10 * Gg] + wb * Pn[c + 11 * Gg]
                + wc * Pn[c + 12 * Gg] + wd * Pn[c + 13 * Gg]  + we * Pn[c + 14 * Gg] + wf * Pn[c + 15 * Gg];
        g_attnP[(size_t)n * Gg + c] = a;
    }
}

// ---------------- fused per-step kernel: blocks 0..127 = h@Wh GEMM (split-K=2, NT=64), 128..255 = attn ----------------
__global__ void __launch_bounds__(256, 2) step_kernel(const float* __restrict__ Wh) {
    __shared__ unsigned As[2][128][36];
    __shared__ unsigned Bs[2][32][72];
    if (blockIdx.x < 128) {
        gemm_body<3, 64>(blockIdx.x & 63, blockIdx.x >> 6, Wh, nullptr, nullptr, nullptr, As, Bs);
    } else {
        attn_body(blockIdx.x - 128, (float*)&As[0][0][0], (float*)&Bs[0][0][0]);
    }
}

// ---------------- gates: z = z0+z1+xw+attnP+b; LSTM update; store h into hn[t] ----------------
__device__ __forceinline__ float4 f4add5(float4 a, float4 b, float4 c, float4 d, float4 e) {
    return make_float4(a.x + b.x + c.x + d.x + e.x,
                       a.y + b.y + c.y + d.y + e.y,
                       a.z + b.z + c.z + d.z + e.z,
                       a.w + b.w + c.w + d.w + e.w);
}
__device__ __forceinline__ void lstm1(float zi, float zf, float zo, float zg,
                                      float cin, float& cout, float& hout) {
    float si = 1.f / (1.f + expf(-zi));
    float sf = 1.f / (1.f + expf(-zf));
    float so = 1.f / (1.f + expf(-zo));
    float gg = tanhf(zg);
    cout = sf * cin + si * gg;
    hout = so * tanhf(cout);
}

__global__ void gates_kernel(const float* __restrict__ b, int t) {
    int q = blockIdx.x * blockDim.x + threadIdx.x;     // handles 4 h-elements
    if (q >= (Nn * Hh) / 4) return;
    int idx = q * 4;                  // n*H + h
    int n  = idx >> 10;
    int h4 = (idx & (Hh - 1)) >> 2;   // float4 index within gate row

    const float4* z0 = (const float4*)(g_zs + (size_t)n * Gg);
    const float4* z1 = (const float4*)(g_zs + (size_t)(Nn + n) * Gg);
    const float4* xw = (const float4*)(g_xw + ((size_t)t * Nn + n) * Gg);
    const float4* ap = (const float4*)(g_attnP + (size_t)n * Gg);
    const float4* b4 = (const float4*)b;

    float4 zi = f4add5(z0[h4],       z1[h4],       xw[h4],       ap[h4],       b4[h4]);
    float4 zf = f4add5(z0[h4 + 256], z1[h4 + 256], xw[h4 + 256], ap[h4 + 256], b4[h4 + 256]);
    float4 zo = f4add5(z0[h4 + 512], z1[h4 + 512], xw[h4 + 512], ap[h4 + 512], b4[h4 + 512]);
    float4 zg = f4add5(z0[h4 + 768], z1[h4 + 768], xw[h4 + 768], ap[h4 + 768], b4[h4 + 768]);

    float4 cin = ((const float4*)g_c)[q];
    float4 co, ho;
    lstm1(zi.x, zf.x, zo.x, zg.x, cin.x, co.x, ho.x);
    lstm1(zi.y, zf.y, zo.y, zg.y, cin.y, co.y, ho.y);
    lstm1(zi.z, zf.z, zo.z, zg.z, cin.z, co.z, ho.z);
    lstm1(zi.w, zf.w, zo.w, zg.w, cin.w, co.w, ho.w);

    ((float4*)g_c)[q] = co;
    ((float4*)g_h)[q] = ho;
    ((float4*)(g_hn + (size_t)t * Nn * Hh))[q] = ho;
}

// ---------------- per-row log-softmax NLL (masked) ----------------
__global__ void loss_kernel(const int* __restrict__ captions) {
    int r = blockIdx.x;            // r = t*128 + n
    int t = r >> 7, n = r & 127;
    int target = captions[n * TCAP + t + 1];
    const float* s = g_scores + (size_t)r * Vv;
    __shared__ float red[256];
    int tid = threadIdx.x;

    // Vv = 10000 = 2500 float4s
    const float4* s4 = (const float4*)s;
    float m = -1e30f;
    for (int v = tid; v < 2500; v += 256) {
        float4 q = s4[v];
        m = fmaxf(m, fmaxf(fmaxf(q.x, q.y), fmaxf(q.z, q.w)));
    }
    red[tid] = m; __syncthreads();
    for (int o = 128; o > 0; o >>= 1) {
        if (tid < o) red[tid] = fmaxf(red[tid], red[tid + o]);
        __syncthreads();
    }
    float mx = red[0];
    __syncthreads();

    float se = 0.f;
    for (int v = tid; v < 2500; v += 256) {
        float4 q = s4[v];
        se += expf(q.x - mx) + expf(q.y - mx) + expf(q.z - mx) + expf(q.w - mx);
    }
    red[tid] = se; __syncthreads();
    for (int o = 128; o > 0; o >>= 1) {
        if (tid < o) red[tid] += red[tid + o];
        __syncthreads();
    }
    if (tid == 0) {
        float lse = logf(red[0]) + mx;
        float nll = lse - s[target];
        g_nll[r] = (target != 0) ? nll : 0.f;
    }
}

// ---------------- deterministic final reduction ----------------
__global__ void finalize_kernel(float* out) {
    __shared__ float red[256];
    int tid = threadIdx.x;
    float s = 0.f;
    for (int i = tid; i < Tt * Nn; i += 256) s += g_nll[i];
    red[tid] = s; __syncthreads();
    for (int o = 128; o > 0; o >>= 1) {
        if (tid < o) red[tid] += red[tid + o];
        __syncthreads();
    }
    if (tid == 0) out[0] = red[0] * (1.0f / (float)Nn);
}

// ---------------- launch ----------------
extern "C" void kernel_launch(void* const* d_in, const int* in_sizes, int n_in,
                              void* d_out, int out_size) {
    const float* features = (const float*)d_in[0];
    const int*   captions = (const int*)  d_in[1];
    const float* W_embed  = (const float*)d_in[2];
    const float* W_proj   = (const float*)d_in[3];
    const float* b_proj   = (const float*)d_in[4];
    const float* Wx       = (const float*)d_in[5];
    const float* Wh       = (const float*)d_in[6];
    const float* Wattn    = (const float*)d_in[7];
    const float* b        = (const float*)d_in[8];
    const float* W_vocab  = (const float*)d_in[9];
    const float* b_vocab  = (const float*)d_in[10];
    float* out = (float*)d_out;

    proj_kernel<<<dim3(8, 128), 256>>>(features, W_proj, b_proj);
    h0_kernel<<<512, 256>>>();

    // precompute x@Wx for all steps (rows t*128+n) and P = A_flat@Wattn (rows n*16+l)
    gemm_tf32<0, 128><<<dim3(32, 32), 256>>>(Wx,    captions, W_embed, nullptr);
    gemm_tf32<1, 128><<<dim3(32, 16), 256>>>(Wattn, captions, W_embed, nullptr);

    for (int t = 0; t < Tt; t++) {
        step_kernel<<<256, 256>>>(Wh);          // attn + h@Wh (split-K=2), concurrent block roles
        gates_kernel<<<128, 256>>>(b, t);
    }

    gemm_tf32<2, 128><<<dim3(79, 32), 256>>>(W_vocab, captions, W_embed, b_vocab);
    loss_kernel<<<Tt * Nn, 256>>>(captions);
    finalize_kernel<<<1, 256>>>(out);
}

// round 15
// speedup vs baseline: 1.4378x; 1.4378x over previous
#include <cuda_runtime.h>
#include <cuda_bf16.h>
#include <math.h>

// Problem dims
#define Nn    128
#define Tt    32
#define TCAP  33
#define Dd    400
#define Ww    512
#define Hh    1024
#define Vv    10000
#define Gg    4096   // 4*H

// ---------------- device scratch (static, allocation-guard compliant) ----------------
__device__ __align__(16) float g_A[Nn * 16 * Hh];              // A_flat [n][l][h], 8 MB
__device__ __align__(16) float g_h[Nn * Hh];                   // current hidden
__device__ __align__(16) float g_c[Nn * Hh];                   // current cell
__device__ __align__(16) float g_attnP[Nn * Gg];               // (attn @ Wattn), 2 MB
__device__ __align__(16) float g_xw[(size_t)Tt * Nn * Gg];     // x_t @ Wx, rows t*128+n, 64 MB
__device__ __align__(16) float g_P[(size_t)Nn * 16 * Gg];      // A_flat @ Wattn, rows n*16+l, 32 MB
__device__ __align__(16) float g_zs[2 * Nn * Gg];              // split-K partials of h@Wh, 4 MB
__device__ __align__(16) float g_hn[(size_t)Tt * Nn * Hh];     // hidden states, rows t*128+n, 16 MB
__device__ __align__(16) float g_scores[(size_t)Tt * Nn * Vv]; // 4096 x 10000 logits, 164 MB
__device__ __align__(16) float g_nll[Tt * Nn];

// ---------------- helpers ----------------
// pack two floats into bf16x2: lo = first arg, hi = second arg
__device__ __forceinline__ unsigned bf2(float lo, float hi) {
    unsigned r;
    asm("cvt.rn.bf16x2.f32 %0, %1, %2;" : "=r"(r) : "f"(hi), "f"(lo));
    return r;
}
__device__ __forceinline__ void mma_bf16(float* c, const unsigned* a, const unsigned* b) {
    asm("mma.sync.aligned.m16n8k16.row.col.f32.bf16.bf16.f32 "
        "{%0,%1,%2,%3}, {%4,%5,%6,%7}, {%8,%9}, {%0,%1,%2,%3};"
        : "+f"(c[0]), "+f"(c[1]), "+f"(c[2]), "+f"(c[3])
        : "r"(a[0]), "r"(a[1]), "r"(a[2]), "r"(a[3]), "r"(b[0]), "r"(b[1]));
}

// ---------------- 1) feature projection: A[n][l][h] = sum_d F[n][d][l]*Wp[d][h] + bp[h] ----------------
__global__ void proj_kernel(const float* __restrict__ features,
                            const float* __restrict__ W_proj,
                            const float* __restrict__ b_proj) {
    __shared__ float Fs[Dd * 16];
    int n  = blockIdx.y;
    int h0 = blockIdx.x * 128;
    int t  = threadIdx.x;

    const float* F = features + (size_t)n * Dd * 16;
    for (int i = t; i < Dd * 16; i += 256) Fs[i] = F[i];
    __syncthreads();

    int h  = h0 + (t & 127);
    int lb = (t >> 7) * 8;
    float acc[8];
    #pragma unroll
    for (int i = 0; i < 8; i++) acc[i] = 0.f;

    for (int d = 0; d < Dd; d++) {
        float w = W_proj[(size_t)d * Hh + h];
        #pragma unroll
        for (int i = 0; i < 8; i++) acc[i] += Fs[d * 16 + lb + i] * w;
    }
    float bp = b_proj[h];
    #pragma unroll
    for (int i = 0; i < 8; i++)
        g_A[(size_t)n * 16 * Hh + (lb + i) * Hh + h] = acc[i] + bp;
}

// ---------------- 2) h0 = mean over l; init h and c ----------------
__global__ void h0_kernel() {
    int idx = blockIdx.x * blockDim.x + threadIdx.x;
    if (idx >= Nn * Hh) return;
    int n = idx >> 10;
    float s = 0.f;
    #pragma unroll
    for (int l = 0; l < 16; l++) s += g_A[(size_t)n * 16 * Hh + l * Hh + (idx & (Hh - 1))];
    s *= (1.0f / 16.0f);
    g_h[idx] = s;
    g_c[idx] = s;
}

// ---------------- bf16 tensor-core GEMM body: C[M x NTILE] = A[M x K] * B[K x NTILE] ----------------
// Block tile 128 x NT (NT = 64 or 128), BK=32, 256 threads.
// mma.sync m16n8k16 bf16 (fp32 accum). Inputs packed as bf16x2 pairs over k.
// A smem: As[row][k2] (k2 = k/2, 16 per BK), pad to 20. B smem: Bs[k2][col], pad NT+8.
// NT=64 : warps 4M x 2N, warp tile 32x32 (MT=2)  -- MODE 3 (step GEMM)
// NT=128: warps 2M x 4N, warp tile 64x32 (MT=4)  -- batch GEMMs
// MODE 0: xw   A = embedding gather (K=512),  B=Wx,      C=g_xw
// MODE 1: P    A = g_A   (2048 rows, K=1024), B=Wattn,   C=g_P
// MODE 2: voc  A = g_hn  (4096 rows, K=1024), B=W_vocab, C=g_scores (+bias, col guard)
// MODE 3: hWh  A = g_h   (128 rows),  split-K=2 over K=1024 via 'by', C=g_zs
template<int MODE, int NT>
__device__ __forceinline__ void gemm_body(
    int bx, int by,
    const float* __restrict__ Bmat,
    const int*   __restrict__ captions,
    const float* __restrict__ W_embed,
    const float* __restrict__ bias,
    unsigned (*As)[20], unsigned (*Bs)[NT + 8])
{
    constexpr int KLEN  = (MODE == 0 || MODE == 3) ? 512 : 1024;
    constexpr int NITER = KLEN / 32;
    constexpr int LDB   = (MODE == 2) ? Vv : Gg;
    constexpr int LDC   = (MODE == 2) ? Vv : Gg;
    constexpr int MT    = (NT == 64) ? 2 : 4;       // m16 fragments per warp
    constexpr int CPT   = NT / 16;                  // B-fill cols per thread (4 or 8)
    constexpr int NBF4  = CPT / 4;                  // float4 chunks per row (1 or 2)

    const int tid  = threadIdx.x;
    const int lane = tid & 31;
    const int warp = tid >> 5;
    const int wm   = (NT == 64) ? (warp >> 1) * 32 : (warp >> 2) * 64;
    const int wn   = (NT == 64) ? (warp & 1) * 32  : (warp & 3) * 32;
    const int gid  = lane >> 2;            // 0..7
    const int tig  = lane & 3;             // 0..3
    const int n0   = bx * NT;

    int m0, kbase;
    float* C;
    if (MODE == 3) {
        m0 = 0; kbase = by * 512;
        C = g_zs + (size_t)by * (Nn * Gg);
    } else {
        m0 = by * 128; kbase = 0;
        C = (MODE == 0) ? g_xw : ((MODE == 1) ? g_P : g_scores);
    }

    // ---- A fill: thread owns row lm, 16 consecutive k at float offset gsel*16 ----
    const int lm   = tid >> 1;             // 0..127
    const int gsel = tid & 1;              // k2 offset 0 or 8
    const float* aptr;
    {
        int gr = m0 + lm;
        const float* rowp;
        if (MODE == 0) {
            int tok = captions[(gr & 127) * TCAP + (gr >> 7)];
            rowp = W_embed + (size_t)tok * Ww;
        } else if (MODE == 1) {
            rowp = g_A + (size_t)gr * Hh;
        } else if (MODE == 2) {
            rowp = g_hn + (size_t)gr * Hh;
        } else {
            rowp = g_h + (size_t)gr * Hh;
        }
        aptr = rowp + kbase + gsel * 16;
    }

    // ---- B fill: thread owns k2-row k2r (gmem rows 2k2r, 2k2r+1), CPT consecutive cols ----
    const int k2r     = tid >> 4;              // 0..15
    const int colbase = (tid & 15) * CPT;      // 0..NT-CPT
    const float* bptr = Bmat + (size_t)(kbase + 2 * k2r) * LDB + n0 + colbase;
    const bool bok = (MODE != 2) || (n0 + colbase + CPT - 1 < Vv);   // chunk all-or-nothing

    // ---- initial gmem prefetch into regs ----
    float4 av0, av1, av2, av3;
    float4 blo[NBF4], bhi[NBF4];
    av0 = *(const float4*)(aptr);     av1 = *(const float4*)(aptr + 4);
    av2 = *(const float4*)(aptr + 8); av3 = *(const float4*)(aptr + 12);
    aptr += 32;
    if (bok) {
        #pragma unroll
        for (int q = 0; q < NBF4; q++) {
            blo[q] = *(const float4*)(bptr + 4 * q);
            bhi[q] = *(const float4*)(bptr + LDB + 4 * q);
        }
    } else {
        #pragma unroll
        for (int q = 0; q < NBF4; q++) {
            blo[q] = make_float4(0.f, 0.f, 0.f, 0.f); bhi[q] = blo[q];
        }
    }
    bptr += (size_t)32 * LDB;

    float acc[MT][4][4];
    #pragma unroll
    for (int mt = 0; mt < MT; mt++)
        #pragma unroll
        for (int nt = 0; nt < 4; nt++)
            #pragma unroll
            for (int q = 0; q < 4; q++) acc[mt][nt][q] = 0.f;

    for (int it = 0; it < NITER; it++) {
        // ---- store prefetched tile to smem (bf16x2 packed over k) ----
        {
            int lkk2 = gsel * 8;
            *(uint4*)&As[lm][lkk2] = make_uint4(bf2(av0.x, av0.y), bf2(av0.z, av0.w),
                                                bf2(av1.x, av1.y), bf2(av1.z, av1.w));
            *(uint4*)&As[lm][lkk2 + 4] = make_uint4(bf2(av2.x, av2.y), bf2(av2.z, av2.w),
                                                    bf2(av3.x, av3.y), bf2(av3.z, av3.w));
            #pragma unroll
            for (int q = 0; q < NBF4; q++) {
                *(uint4*)&Bs[k2r][colbase + 4 * q] =
                    make_uint4(bf2(blo[q].x, bhi[q].x), bf2(blo[q].y, bhi[q].y),
                               bf2(blo[q].z, bhi[q].z), bf2(blo[q].w, bhi[q].w));
            }
        }
        __syncthreads();

        // ---- prefetch next tile (latency overlaps compute) ----
        if (it + 1 < NITER) {
            av0 = *(const float4*)(aptr);     av1 = *(const float4*)(aptr + 4);
            av2 = *(const float4*)(aptr + 8); av3 = *(const float4*)(aptr + 12);
            aptr += 32;
            if (bok) {
                #pragma unroll
                for (int q = 0; q < NBF4; q++) {
                    blo[q] = *(const float4*)(bptr + 4 * q);
                    bhi[q] = *(const float4*)(bptr + LDB + 4 * q);
                }
            }
            bptr += (size_t)32 * LDB;
        }

        // ---- compute: 2 k16 steps ----
        #pragma unroll
        for (int s = 0; s < 2; s++) {
            const int s8 = s * 8;             // k2 base of this k16 step
            unsigned bfr[4][2];
            #pragma unroll
            for (int nt = 0; nt < 4; nt++) {
                int ccol = wn + nt * 8 + gid;
                bfr[nt][0] = Bs[s8 + tig][ccol];
                bfr[nt][1] = Bs[s8 + tig + 4][ccol];
            }
            #pragma unroll
            for (int half = 0; half < MT / 2; half++) {
                unsigned afr[2][4];
                #pragma unroll
                for (int m2 = 0; m2 < 2; m2++) {
                    int r = wm + (half * 2 + m2) * 16 + gid;
                    afr[m2][0] = As[r][s8 + tig];
                    afr[m2][1] = As[r + 8][s8 + tig];
                    afr[m2][2] = As[r][s8 + tig + 4];
                    afr[m2][3] = As[r + 8][s8 + tig + 4];
                }
                #pragma unroll
                for (int m2 = 0; m2 < 2; m2++)
                    #pragma unroll
                    for (int nt = 0; nt < 4; nt++)
                        mma_bf16(acc[half * 2 + m2][nt], afr[m2], bfr[nt]);
            }
        }
        __syncthreads();
    }

    // ---- epilogue: c-frag layout -> gmem (float2 stores; col even, Vv even) ----
    #pragma unroll
    for (int mt = 0; mt < MT; mt++) {
        #pragma unroll
        for (int nt = 0; nt < 4; nt++) {
            int col = n0 + wn + nt * 8 + 2 * tig;
            if (MODE != 2 || col < Vv) {
                float b0 = 0.f, b1 = 0.f;
                if (MODE == 2) { b0 = bias[col]; b1 = bias[col + 1]; }
                int r0 = m0 + wm + mt * 16 + gid;
                float2 lo = make_float2(acc[mt][nt][0] + b0, acc[mt][nt][1] + b1);
                float2 hi = make_float2(acc[mt][nt][2] + b0, acc[mt][nt][3] + b1);
                *(float2*)&C[(size_t)r0 * LDC + col]       = lo;
                *(float2*)&C[(size_t)(r0 + 8) * LDC + col] = hi;
            }
        }
    }
}

template<int MODE, int NT>
__global__ void __launch_bounds__(256, 2) gemm_bf16(
    const float* __restrict__ Bmat,
    const int*   __restrict__ captions,
    const float* __restrict__ W_embed,
    const float* __restrict__ bias)
{
    __shared__ unsigned As[128][20];
    __shared__ unsigned Bs[16][NT + 8];
    gemm_body<MODE, NT>(blockIdx.x, blockIdx.y, Bmat, captions, W_embed, bias, As, Bs);
}

// ---------------- attention body: w = softmax(h.A/sqrt(H)); attnP = sum_l w_l P[n,l,:] ----------------
__device__ __forceinline__ void attn_body(int n, float* ph, float* scbuf) {
    float* sc  = scbuf;
    float* wsm = scbuf + 16;
    int t = threadIdx.x;

    #pragma unroll
    for (int i = 0; i < 4; i++) ph[t + 256 * i] = g_h[(size_t)n * Hh + t + 256 * i];
    __syncthreads();

    int warp = t >> 5, lane = t & 31;
    #pragma unroll
    for (int li = 0; li < 2; li++) {
        int l = warp + 8 * li;
        const float* Arow = g_A + (size_t)n * 16 * Hh + (size_t)l * Hh;
        float s = 0.f;
        for (int h = lane; h < Hh; h += 32) s += ph[h] * Arow[h];
        #pragma unroll
        for (int o = 16; o > 0; o >>= 1) s += __shfl_xor_sync(0xffffffff, s, o);
        if (lane == 0) sc[l] = s;
    }
    __syncthreads();

    if (t < 32) {
        float v = (t < 16) ? sc[t] * 0.03125f : -1e30f;   // 1/sqrt(1024)
        float m = v;
        #pragma unroll
        for (int o = 16; o > 0; o >>= 1) m = fmaxf(m, __shfl_xor_sync(0xffffffff, m, o));
        float e = (t < 16) ? expf(v - m) : 0.f;
        float se = e;
        #pragma unroll
        for (int o = 16; o > 0; o >>= 1) se += __shfl_xor_sync(0xffffffff, se, o);
        if (t < 16) wsm[t] = e / se;
    }
    __syncthreads();

    const float* Pn = g_P + (size_t)n * 16 * Gg;
    float w0 = wsm[0], w1 = wsm[1], w2 = wsm[2], w3 = wsm[3];
    float w4 = wsm[4], w5 = wsm[5], w6 = wsm[6], w7 = wsm[7];
    float w8 = wsm[8], w9 = wsm[9], wa = wsm[10], wb = wsm[11];
    float wc = wsm[12], wd = wsm[13], we = wsm[14], wf = wsm[15];
    for (int c = t; c < Gg; c += 256) {
        float a = w0 * Pn[c]           + w1 * Pn[c + Gg]       + w2 * Pn[c + 2 * Gg]  + w3 * Pn[c + 3 * Gg]
                + w4 * Pn[c + 4 * Gg]  + w5 * Pn[c + 5 * Gg]   + w6 * Pn[c + 6 * Gg]  + w7 * Pn[c + 7 * Gg]
                + w8 * Pn[c + 8 * Gg]  + w9 * Pn[c + 9 * Gg]   + wa * Pn[c + 10 * Gg] + wb * Pn[c + 11 * Gg]
                + wc * Pn[c + 12 * Gg] + wd * Pn[c + 13 * Gg]  + we * Pn[c + 14 * Gg] + wf * Pn[c + 15 * Gg];
        g_attnP[(size_t)n * Gg + c] = a;
    }
}

// ---------------- fused per-step kernel: blocks 0..127 = h@Wh GEMM (split-K=2, NT=64), 128..255 = attn ----------------
__global__ void __launch_bounds__(256, 2) step_kernel(const float* __restrict__ Wh) {
    __shared__ unsigned As[128][20];
    __shared__ unsigned Bs[16][72];
    if (blockIdx.x < 128) {
        gemm_body<3, 64>(blockIdx.x & 63, blockIdx.x >> 6, Wh, nullptr, nullptr, nullptr, As, Bs);
    } else {
        attn_body(blockIdx.x - 128, (float*)&As[0][0], (float*)&Bs[0][0]);
    }
}

// ---------------- gates: z = z0+z1+xw+attnP+b; LSTM update; store h into hn[t] ----------------
__device__ __forceinline__ float4 f4add5(float4 a, float4 b, float4 c, float4 d, float4 e) {
    return make_float4(a.x + b.x + c.x + d.x + e.x,
                       a.y + b.y + c.y + d.y + e.y,
                       a.z + b.z + c.z + d.z + e.z,
                       a.w + b.w + c.w + d.w + e.w);
}
__device__ __forceinline__ void lstm1(float zi, float zf, float zo, float zg,
                                      float cin, float& cout, float& hout) {
    float si = 1.f / (1.f + expf(-zi));
    float sf = 1.f / (1.f + expf(-zf));
    float so = 1.f / (1.f + expf(-zo));
    float gg = tanhf(zg);
    cout = sf * cin + si * gg;
    hout = so * tanhf(cout);
}

__global__ void gates_kernel(const float* __restrict__ b, int t) {
    int q = blockIdx.x * blockDim.x + threadIdx.x;     // handles 4 h-elements
    if (q >= (Nn * Hh) / 4) return;
    int idx = q * 4;                  // n*H + h
    int n  = idx >> 10;
    int h4 = (idx & (Hh - 1)) >> 2;   // float4 index within gate row

    const float4* z0 = (const float4*)(g_zs + (size_t)n * Gg);
    const float4* z1 = (const float4*)(g_zs + (size_t)(Nn + n) * Gg);
    const float4* xw = (const float4*)(g_xw + ((size_t)t * Nn + n) * Gg);
    const float4* ap = (const float4*)(g_attnP + (size_t)n * Gg);
    const float4* b4 = (const float4*)b;

    float4 zi = f4add5(z0[h4],       z1[h4],       xw[h4],       ap[h4],       b4[h4]);
    float4 zf = f4add5(z0[h4 + 256], z1[h4 + 256], xw[h4 + 256], ap[h4 + 256], b4[h4 + 256]);
    float4 zo = f4add5(z0[h4 + 512], z1[h4 + 512], xw[h4 + 512], ap[h4 + 512], b4[h4 + 512]);
    float4 zg = f4add5(z0[h4 + 768], z1[h4 + 768], xw[h4 + 768], ap[h4 + 768], b4[h4 + 768]);

    float4 cin = ((const float4*)g_c)[q];
    float4 co, ho;
    lstm1(zi.x, zf.x, zo.x, zg.x, cin.x, co.x, ho.x);
    lstm1(zi.y, zf.y, zo.y, zg.y, cin.y, co.y, ho.y);
    lstm1(zi.z, zf.z, zo.z, zg.z, cin.z, co.z, ho.z);
    lstm1(zi.w, zf.w, zo.w, zg.w, cin.w, co.w, ho.w);

    ((float4*)g_c)[q] = co;
    ((float4*)g_h)[q] = ho;
    ((float4*)(g_hn + (size_t)t * Nn * Hh))[q] = ho;
}

// ---------------- per-row log-softmax NLL (masked) ----------------
__global__ void loss_kernel(const int* __restrict__ captions) {
    int r = blockIdx.x;            // r = t*128 + n
    int t = r >> 7, n = r & 127;
    int target = captions[n * TCAP + t + 1];
    const float* s = g_scores + (size_t)r * Vv;
    __shared__ float red[256];
    int tid = threadIdx.x;

    // Vv = 10000 = 2500 float4s
    const float4* s4 = (const float4*)s;
    float m = -1e30f;
    for (int v = tid; v < 2500; v += 256) {
        float4 q = s4[v];
        m = fmaxf(m, fmaxf(fmaxf(q.x, q.y), fmaxf(q.z, q.w)));
    }
    red[tid] = m; __syncthreads();
    for (int o = 128; o > 0; o >>= 1) {
        if (tid < o) red[tid] = fmaxf(red[tid], red[tid + o]);
        __syncthreads();
    }
    float mx = red[0];
    __syncthreads();

    float se = 0.f;
    for (int v = tid; v < 2500; v += 256) {
        float4 q = s4[v];
        se += expf(q.x - mx) + expf(q.y - mx) + expf(q.z - mx) + expf(q.w - mx);
    }
    red[tid] = se; __syncthreads();
    for (int o = 128; o > 0; o >>= 1) {
        if (tid < o) red[tid] += red[tid + o];
        __syncthreads();
    }
    if (tid == 0) {
        float lse = logf(red[0]) + mx;
        float nll = lse - s[target];
        g_nll[r] = (target != 0) ? nll : 0.f;
    }
}

// ---------------- deterministic final reduction ----------------
__global__ void finalize_kernel(float* out) {
    __shared__ float red[256];
    int tid = threadIdx.x;
    float s = 0.f;
    for (int i = tid; i < Tt * Nn; i += 256) s += g_nll[i];
    red[tid] = s; __syncthreads();
    for (int o = 128; o > 0; o >>= 1) {
        if (tid < o) red[tid] += red[tid + o];
        __syncthreads();
    }
    if (tid == 0) out[0] = red[0] * (1.0f / (float)Nn);
}

// ---------------- launch ----------------
extern "C" void kernel_launch(void* const* d_in, const int* in_sizes, int n_in,
                              void* d_out, int out_size) {
    const float* features = (const float*)d_in[0];
    const int*   captions = (const int*)  d_in[1];
    const float* W_embed  = (const float*)d_in[2];
    const float* W_proj   = (const float*)d_in[3];
    const float* b_proj   = (const float*)d_in[4];
    const float* Wx       = (const float*)d_in[5];
    const float* Wh       = (const float*)d_in[6];
    const float* Wattn    = (const float*)d_in[7];
    const float* b        = (const float*)d_in[8];
    const float* W_vocab  = (const float*)d_in[9];
    const float* b_vocab  = (const float*)d_in[10];
    float* out = (float*)d_out;

    proj_kernel<<<dim3(8, 128), 256>>>(features, W_proj, b_proj);
    h0_kernel<<<512, 256>>>();

    // precompute x@Wx for all steps (rows t*128+n) and P = A_flat@Wattn (rows n*16+l)
    gemm_bf16<0, 128><<<dim3(32, 32), 256>>>(Wx,    captions, W_embed, nullptr);
    gemm_bf16<1, 128><<<dim3(32, 16), 256>>>(Wattn, captions, W_embed, nullptr);

    for (int t = 0; t < Tt; t++) {
        step_kernel<<<256, 256>>>(Wh);          // attn + h@Wh (split-K=2), concurrent block roles
        gates_kernel<<<128, 256>>>(b, t);
    }

    gemm_bf16<2, 128><<<dim3(79, 32), 256>>>(W_vocab, captions, W_embed, b_vocab);
    loss_kernel<<<Tt * Nn, 256>>>(captions);
    finalize_kernel<<<1, 256>>>(out);
}